// round 7
// baseline (speedup 1.0000x reference)
#include <cuda_runtime.h>
#include <cuda_bf16.h>
#include <math.h>
#include <cstdint>

#define B_ 4
#define D_ 512
#define S_ 2048
#define L_ 8921

// bf16x2 split operands
__device__ __nv_bfloat16 g_Kh[B_ * S_ * D_];
__device__ __nv_bfloat16 g_Kl[B_ * S_ * D_];
__device__ __nv_bfloat16 g_VTh[B_ * D_ * S_];
__device__ __nv_bfloat16 g_VTl[B_ * D_ * S_];
__device__ __nv_bfloat16 g_Qh[L_ * D_];
__device__ __nv_bfloat16 g_Ql[L_ * D_];
__device__ __nv_bfloat16 g_Ah[(size_t)B_ * L_ * S_];
__device__ __nv_bfloat16 g_Al[(size_t)B_ * L_ * S_];
__device__ __nv_bfloat16 g_Hth[B_ * S_ * D_];   // H^T [B,S,D] hi
__device__ __nv_bfloat16 g_Htl[B_ * S_ * D_];   // H^T [B,S,D] lo
__device__ __nv_bfloat16 g_Wh[2 * D_ * D_];     // Wk | Wv hi
__device__ __nv_bfloat16 g_Wl[2 * D_ * D_];     // Wk | Wv lo

// ---------------------------------------------------------------------------
// helpers
// ---------------------------------------------------------------------------
__device__ __forceinline__ uint32_t smem_to_u32(const void* p) {
    uint32_t a;
    asm("{ .reg .u64 t; cvta.to.shared.u64 t, %1; cvt.u32.u64 %0, t; }" : "=r"(a) : "l"(p));
    return a;
}
__device__ __forceinline__ void cp_async16(uint32_t dst, const void* src) {
    asm volatile("cp.async.cg.shared.global [%0], [%1], 16;" :: "r"(dst), "l"(src));
}
#define CP_COMMIT() asm volatile("cp.async.commit_group;" ::: "memory")
#define CP_WAIT(n)  asm volatile("cp.async.wait_group %0;" :: "n"(n) : "memory")

__device__ __forceinline__ void mma_bf16(float* d, const uint32_t* a, const uint32_t* b) {
    asm volatile(
        "mma.sync.aligned.m16n8k16.row.col.f32.bf16.bf16.f32 "
        "{%0,%1,%2,%3}, {%4,%5,%6,%7}, {%8,%9}, {%0,%1,%2,%3};"
        : "+f"(d[0]), "+f"(d[1]), "+f"(d[2]), "+f"(d[3])
        : "r"(a[0]), "r"(a[1]), "r"(a[2]), "r"(a[3]), "r"(b[0]), "r"(b[1]));
}
__device__ __forceinline__ void ldmx4(uint32_t* r, uint32_t addr) {
    asm volatile("ldmatrix.sync.aligned.m8n8.x4.shared.b16 {%0,%1,%2,%3}, [%4];"
        : "=r"(r[0]), "=r"(r[1]), "=r"(r[2]), "=r"(r[3]) : "r"(addr));
}

__device__ __forceinline__ float elu_f(float x) { return x > 0.f ? x : expm1f(x); }

__device__ __forceinline__ void split_bf16(float x, __nv_bfloat16& hi, __nv_bfloat16& lo) {
    hi = __float2bfloat16(x);
    lo = __float2bfloat16(x - __bfloat162float(hi));
}

// ===========================================================================
// Shared GEMM tile config (bf16x3 split mma.sync)
// Block 128x128, TK=32, 8 warps (warp tile 64x32), true double-buffer pipe,
// 2 CTAs/SM.
// ===========================================================================
#define TM 128
#define TN 128
#define TK 32
#define ROWB 80                          // 32 bf16 = 64B + 16B pad
#define SUB  (128 * ROWB)                // 10240 per sub-tile
#define STAGE (4 * SUB)                  // Ah | Al | Bh | Bl = 40960
#define GEMM_SMEM (2 * STAGE)            // 81920 -> 2 CTAs/SM

// ---------------------------------------------------------------------------
// Main GEMM: C[m,n] = sum_k A[m,k]*B[n,k], fp32 output
// ---------------------------------------------------------------------------
__global__ __launch_bounds__(256, 2) void gemm_mma(
    const __nv_bfloat16* __restrict__ Ah, const __nv_bfloat16* __restrict__ Al,
    int lda, size_t sA,
    const __nv_bfloat16* __restrict__ Bh, const __nv_bfloat16* __restrict__ Bl,
    int ldb, size_t sB,
    float* __restrict__ C, int ldc, size_t sC,
    int kblocks, int Mtotal)
{
    extern __shared__ char smem[];
    const uint32_t sm0 = smem_to_u32(smem);

    const int t    = threadIdx.x;
    const int wid  = t >> 5, lane = t & 31;
    const int gid  = lane >> 2, tig = lane & 3;
    const int b    = blockIdx.z;
    const int m0   = blockIdx.y * TM;
    const int n0   = blockIdx.x * TN;

    Ah += (size_t)b * sA;  Al += (size_t)b * sA;
    Bh += (size_t)b * sB;  Bl += (size_t)b * sB;
    C  += (size_t)b * sC;

    const int wm0 = (wid & 1) * 64;
    const int wn0 = (wid >> 1) * 32;

    float acc[4][4][4];
#pragma unroll
    for (int i = 0; i < 4; i++)
#pragma unroll
        for (int j = 0; j < 4; j++)
#pragma unroll
            for (int q = 0; q < 4; q++) acc[i][j][q] = 0.f;

    auto issue_stage = [&](int kb, int stg) {
        const uint32_t sbase = sm0 + stg * STAGE;
        const int k0 = kb * TK;
#pragma unroll
        for (int it = 0; it < 8; it++) {
            int idx = t + it * 256;
            int sub = idx >> 9;
            int r   = (idx >> 2) & 127;
            int c   = idx & 3;
            uint32_t dst = sbase + sub * SUB + r * ROWB + c * 16;
            const __nv_bfloat16* src;
            if (sub < 2) {
                int gr = m0 + r; if (gr >= Mtotal) gr = Mtotal - 1;
                src = (sub == 0 ? Ah : Al) + (size_t)gr * lda + k0 + c * 8;
            } else {
                src = (sub == 2 ? Bh : Bl) + (size_t)(n0 + r) * ldb + k0 + c * 8;
            }
            cp_async16(dst, src);
        }
    };

    const int arow = lane & 15;
    const int aoff = (lane >> 4) * 16;
    const int bprow = ((lane >> 4) & 1) * 8 + (lane & 7);
    const int bpoff = ((lane >> 3) & 1) * 16;

    issue_stage(0, 0);
    CP_COMMIT();

    for (int kb = 0; kb < kblocks; kb++) {
        // prefetch next stage FIRST, then wait only for the stage we consume
        if (kb + 1 < kblocks) {
            issue_stage(kb + 1, (kb + 1) & 1);
            CP_COMMIT();
            CP_WAIT(1);          // stage kb complete; kb+1 still in flight
        } else {
            CP_WAIT(0);
        }
        __syncthreads();

        const uint32_t sbase = sm0 + (kb & 1) * STAGE;

#pragma unroll
        for (int ks = 0; ks < 2; ks++) {
            uint32_t ah[4][4], al[4][4];
#pragma unroll
            for (int mt = 0; mt < 4; mt++) {
                uint32_t ra = (wm0 + mt * 16 + arow) * ROWB + ks * 32 + aoff;
                ldmx4(ah[mt], sbase + 0 * SUB + ra);
                ldmx4(al[mt], sbase + 1 * SUB + ra);
            }
#pragma unroll
            for (int p = 0; p < 2; p++) {
                uint32_t rb = (wn0 + p * 16 + bprow) * ROWB + ks * 32 + bpoff;
                uint32_t bh4[4], bl4[4];
                ldmx4(bh4, sbase + 2 * SUB + rb);
                ldmx4(bl4, sbase + 3 * SUB + rb);
#pragma unroll
                for (int h = 0; h < 2; h++) {
                    int nt = 2 * p + h;
#pragma unroll
                    for (int mt = 0; mt < 4; mt++) {
                        mma_bf16(acc[mt][nt], ah[mt], bh4 + 2 * h);
                        mma_bf16(acc[mt][nt], ah[mt], bl4 + 2 * h);
                        mma_bf16(acc[mt][nt], al[mt], bh4 + 2 * h);
                    }
                }
            }
        }
        __syncthreads();   // buffer kb&1 free before it is re-issued at kb+2
    }

#pragma unroll
    for (int mt = 0; mt < 4; mt++) {
        int r0 = m0 + wm0 + mt * 16 + gid;
#pragma unroll
        for (int nt = 0; nt < 4; nt++) {
            int c0 = n0 + wn0 + nt * 8 + 2 * tig;
            if (r0 < Mtotal)
                *(float2*)(C + (size_t)r0 * ldc + c0) =
                    make_float2(acc[mt][nt][0], acc[mt][nt][1]);
            if (r0 + 8 < Mtotal)
                *(float2*)(C + (size_t)(r0 + 8) * ldc + c0) =
                    make_float2(acc[mt][nt][2], acc[mt][nt][3]);
        }
    }
}

// ---------------------------------------------------------------------------
// KV GEMM: same core; epilogue = +bias, ELU, bf16 split. biasRow: bias[m] vs bias[n].
// ---------------------------------------------------------------------------
__global__ __launch_bounds__(256, 2) void kv_gemm(
    const __nv_bfloat16* __restrict__ Ah, const __nv_bfloat16* __restrict__ Al,
    int lda, size_t sA,
    const __nv_bfloat16* __restrict__ Bh, const __nv_bfloat16* __restrict__ Bl,
    int ldb, size_t sB,
    __nv_bfloat16* __restrict__ Oh, __nv_bfloat16* __restrict__ Ol,
    int ldc, size_t sC,
    const float* __restrict__ bias, int biasRow,
    int kblocks)
{
    extern __shared__ char smem[];
    const uint32_t sm0 = smem_to_u32(smem);

    const int t    = threadIdx.x;
    const int wid  = t >> 5, lane = t & 31;
    const int gid  = lane >> 2, tig = lane & 3;
    const int b    = blockIdx.z;
    const int m0   = blockIdx.y * TM;
    const int n0   = blockIdx.x * TN;

    Ah += (size_t)b * sA;  Al += (size_t)b * sA;
    Bh += (size_t)b * sB;  Bl += (size_t)b * sB;
    Oh += (size_t)b * sC;  Ol += (size_t)b * sC;

    const int wm0 = (wid & 1) * 64;
    const int wn0 = (wid >> 1) * 32;

    float acc[4][4][4];
#pragma unroll
    for (int i = 0; i < 4; i++)
#pragma unroll
        for (int j = 0; j < 4; j++)
#pragma unroll
            for (int q = 0; q < 4; q++) acc[i][j][q] = 0.f;

    auto issue_stage = [&](int kb, int stg) {
        const uint32_t sbase = sm0 + stg * STAGE;
        const int k0 = kb * TK;
#pragma unroll
        for (int it = 0; it < 8; it++) {
            int idx = t + it * 256;
            int sub = idx >> 9;
            int r   = (idx >> 2) & 127;
            int c   = idx & 3;
            uint32_t dst = sbase + sub * SUB + r * ROWB + c * 16;
            const __nv_bfloat16* src;
            if (sub < 2)
                src = (sub == 0 ? Ah : Al) + (size_t)(m0 + r) * lda + k0 + c * 8;
            else
                src = (sub == 2 ? Bh : Bl) + (size_t)(n0 + r) * ldb + k0 + c * 8;
            cp_async16(dst, src);
        }
    };

    const int arow = lane & 15;
    const int aoff = (lane >> 4) * 16;
    const int bprow = ((lane >> 4) & 1) * 8 + (lane & 7);
    const int bpoff = ((lane >> 3) & 1) * 16;

    issue_stage(0, 0);
    CP_COMMIT();

    for (int kb = 0; kb < kblocks; kb++) {
        if (kb + 1 < kblocks) {
            issue_stage(kb + 1, (kb + 1) & 1);
            CP_COMMIT();
            CP_WAIT(1);
        } else {
            CP_WAIT(0);
        }
        __syncthreads();

        const uint32_t sbase = sm0 + (kb & 1) * STAGE;

#pragma unroll
        for (int ks = 0; ks < 2; ks++) {
            uint32_t ah[4][4], al[4][4];
#pragma unroll
            for (int mt = 0; mt < 4; mt++) {
                uint32_t ra = (wm0 + mt * 16 + arow) * ROWB + ks * 32 + aoff;
                ldmx4(ah[mt], sbase + 0 * SUB + ra);
                ldmx4(al[mt], sbase + 1 * SUB + ra);
            }
#pragma unroll
            for (int p = 0; p < 2; p++) {
                uint32_t rb = (wn0 + p * 16 + bprow) * ROWB + ks * 32 + bpoff;
                uint32_t bh4[4], bl4[4];
                ldmx4(bh4, sbase + 2 * SUB + rb);
                ldmx4(bl4, sbase + 3 * SUB + rb);
#pragma unroll
                for (int h = 0; h < 2; h++) {
                    int nt = 2 * p + h;
#pragma unroll
                    for (int mt = 0; mt < 4; mt++) {
                        mma_bf16(acc[mt][nt], ah[mt], bh4 + 2 * h);
                        mma_bf16(acc[mt][nt], ah[mt], bl4 + 2 * h);
                        mma_bf16(acc[mt][nt], al[mt], bh4 + 2 * h);
                    }
                }
            }
        }
        __syncthreads();
    }

    // epilogue: bias + ELU + split -> bf16x2 stores
#pragma unroll
    for (int mt = 0; mt < 4; mt++) {
        int r0 = m0 + wm0 + mt * 16 + gid;
#pragma unroll
        for (int nt = 0; nt < 4; nt++) {
            int c0 = n0 + wn0 + nt * 8 + 2 * tig;
            float b0, b1, b0r, b1r;
            if (biasRow) {
                b0 = b1 = bias[r0];
                b0r = b1r = bias[r0 + 8];
            } else {
                b0 = b0r = bias[c0];
                b1 = b1r = bias[c0 + 1];
            }
            __nv_bfloat16 h0, l0, h1, l1;
            split_bf16(elu_f(acc[mt][nt][0] + b0), h0, l0);
            split_bf16(elu_f(acc[mt][nt][1] + b1), h1, l1);
            *(__nv_bfloat162*)(Oh + (size_t)r0 * ldc + c0) = __nv_bfloat162(h0, h1);
            *(__nv_bfloat162*)(Ol + (size_t)r0 * ldc + c0) = __nv_bfloat162(l0, l1);
            split_bf16(elu_f(acc[mt][nt][2] + b0r), h0, l0);
            split_bf16(elu_f(acc[mt][nt][3] + b1r), h1, l1);
            *(__nv_bfloat162*)(Oh + (size_t)(r0 + 8) * ldc + c0) = __nv_bfloat162(h0, h1);
            *(__nv_bfloat162*)(Ol + (size_t)(r0 + 8) * ldc + c0) = __nv_bfloat162(l0, l1);
        }
    }
}

// ===========================================================================
// H^T split: H[b,d,s] -> g_Hth/g_Htl [b,s,d] bf16.  Tile 64d x 32s.
// ===========================================================================
__global__ __launch_bounds__(256) void ht_split(const float* __restrict__ H)
{
    __shared__ float tile[64][33];
    const int b = blockIdx.z, s0 = blockIdx.x * 32, d0 = blockIdx.y * 64;
    const int tx = threadIdx.x, ty = threadIdx.y;
    const float* Hb = H + ((size_t)b * D_ + d0) * S_ + s0;

#pragma unroll
    for (int i = 0; i < 8; i++)
        tile[ty * 8 + i][tx] = Hb[(size_t)(ty * 8 + i) * S_ + tx];
    __syncthreads();

    const int t  = ty * 32 + tx;
    const int dd = t & 63, sr = t >> 6;
    const size_t obase = ((size_t)b * S_ + s0) * D_ + d0;
#pragma unroll
    for (int i = 0; i < 8; i++) {
        int s = sr + i * 4;
        float v = tile[dd][s];
        __nv_bfloat16 h, l;
        split_bf16(v, h, l);
        g_Hth[obase + (size_t)s * D_ + dd] = h;
        g_Htl[obase + (size_t)s * D_ + dd] = l;
    }
}

// ===========================================================================
// W split
// ===========================================================================
__global__ __launch_bounds__(256) void w_split(
    const float* __restrict__ Wk, const float* __restrict__ Wv)
{
    int i = blockIdx.x * 1024 + threadIdx.x * 4;
    const float* src = (i < D_ * D_) ? (Wk + i) : (Wv + i - D_ * D_);
    float4 v = *(const float4*)src;
    __nv_bfloat16 h[4], l[4];
    split_bf16(v.x, h[0], l[0]); split_bf16(v.y, h[1], l[1]);
    split_bf16(v.z, h[2], l[2]); split_bf16(v.w, h[3], l[3]);
    *(__nv_bfloat162*)(g_Wh + i)     = __nv_bfloat162(h[0], h[1]);
    *(__nv_bfloat162*)(g_Wh + i + 2) = __nv_bfloat162(h[2], h[3]);
    *(__nv_bfloat162*)(g_Wl + i)     = __nv_bfloat162(l[0], l[1]);
    *(__nv_bfloat162*)(g_Wl + i + 2) = __nv_bfloat162(l[2], l[3]);
}

// ===========================================================================
// Q split
// ===========================================================================
__global__ __launch_bounds__(256) void split_q(const float* __restrict__ Q)
{
    int i = blockIdx.x * 512 + threadIdx.x * 2;
    float2 v = *(const float2*)(Q + i);
    __nv_bfloat16 h0, l0, h1, l1;
    split_bf16(v.x, h0, l0);
    split_bf16(v.y, h1, l1);
    *(__nv_bfloat162*)(g_Qh + i) = __nv_bfloat162(h0, h1);
    *(__nv_bfloat162*)(g_Ql + i) = __nv_bfloat162(l0, l1);
}

// ===========================================================================
// In-place row softmax over S=2048 (+ bf16x2 split)
// ===========================================================================
__global__ __launch_bounds__(256) void softmax_kernel(float* __restrict__ A)
{
    const size_t row = blockIdx.x;
    float* p = A + row * (size_t)S_;
    __nv_bfloat16* ph = g_Ah + row * (size_t)S_;
    __nv_bfloat16* pl = g_Al + row * (size_t)S_;
    const int t = threadIdx.x;
    const int lane = t & 31, wid = t >> 5;

    float4 va = *(const float4*)(p + t * 4);
    float4 vb = *(const float4*)(p + 1024 + t * 4);

    float m = fmaxf(fmaxf(fmaxf(va.x, va.y), fmaxf(va.z, va.w)),
                    fmaxf(fmaxf(vb.x, vb.y), fmaxf(vb.z, vb.w)));
#pragma unroll
    for (int o = 16; o > 0; o >>= 1) m = fmaxf(m, __shfl_xor_sync(0xffffffffu, m, o));

    __shared__ float red[8];
    if (lane == 0) red[wid] = m;
    __syncthreads();
    {
        float r = red[lane & 7];
#pragma unroll
        for (int o = 4; o > 0; o >>= 1) r = fmaxf(r, __shfl_xor_sync(0xffffffffu, r, o));
        m = r;
    }

    va.x = __expf(va.x - m); va.y = __expf(va.y - m);
    va.z = __expf(va.z - m); va.w = __expf(va.w - m);
    vb.x = __expf(vb.x - m); vb.y = __expf(vb.y - m);
    vb.z = __expf(vb.z - m); vb.w = __expf(vb.w - m);

    float s = va.x + va.y + va.z + va.w + vb.x + vb.y + vb.z + vb.w;
#pragma unroll
    for (int o = 16; o > 0; o >>= 1) s += __shfl_xor_sync(0xffffffffu, s, o);
    __syncthreads();
    if (lane == 0) red[wid] = s;
    __syncthreads();
    {
        float r = red[lane & 7];
#pragma unroll
        for (int o = 4; o > 0; o >>= 1) r += __shfl_xor_sync(0xffffffffu, r, o);
        s = r;
    }
    float inv = 1.f / s;

    va.x *= inv; va.y *= inv; va.z *= inv; va.w *= inv;
    vb.x *= inv; vb.y *= inv; vb.z *= inv; vb.w *= inv;

    *(float4*)(p + t * 4) = va;
    *(float4*)(p + 1024 + t * 4) = vb;

    __nv_bfloat16 h[8], l[8];
    split_bf16(va.x, h[0], l[0]); split_bf16(va.y, h[1], l[1]);
    split_bf16(va.z, h[2], l[2]); split_bf16(va.w, h[3], l[3]);
    split_bf16(vb.x, h[4], l[4]); split_bf16(vb.y, h[5], l[5]);
    split_bf16(vb.z, h[6], l[6]); split_bf16(vb.w, h[7], l[7]);

    *(__nv_bfloat162*)(ph + t * 4)     = __nv_bfloat162(h[0], h[1]);
    *(__nv_bfloat162*)(ph + t * 4 + 2) = __nv_bfloat162(h[2], h[3]);
    *(__nv_bfloat162*)(ph + 1024 + t * 4)     = __nv_bfloat162(h[4], h[5]);
    *(__nv_bfloat162*)(ph + 1024 + t * 4 + 2) = __nv_bfloat162(h[6], h[7]);
    *(__nv_bfloat162*)(pl + t * 4)     = __nv_bfloat162(l[0], l[1]);
    *(__nv_bfloat162*)(pl + t * 4 + 2) = __nv_bfloat162(l[2], l[3]);
    *(__nv_bfloat162*)(pl + 1024 + t * 4)     = __nv_bfloat162(l[4], l[5]);
    *(__nv_bfloat162*)(pl + 1024 + t * 4 + 2) = __nv_bfloat162(l[6], l[7]);
}

// ===========================================================================
extern "C" void kernel_launch(void* const* d_in, const int* in_sizes, int n_in,
                              void* d_out, int out_size)
{
    const float* H  = (const float*)d_in[0];
    const float* Wk = (const float*)d_in[1];
    const float* bk = (const float*)d_in[2];
    const float* Wv = (const float*)d_in[3];
    const float* bv = (const float*)d_in[4];
    const float* Q  = (const float*)d_in[5];

    float* out  = (float*)d_out;
    float* Cout = out;                          // [B, L, D]
    float* Aout = out + (size_t)B_ * L_ * D_;   // [B, L, S]

    static __nv_bfloat16 *gKh, *gKl, *gVTh, *gVTl, *gQh, *gQl, *gAh, *gAl;
    static __nv_bfloat16 *gHth, *gHtl, *gWh, *gWl;
    static bool init = false;
    if (!init) {
        cudaGetSymbolAddress((void**)&gKh,  g_Kh);
        cudaGetSymbolAddress((void**)&gKl,  g_Kl);
        cudaGetSymbolAddress((void**)&gVTh, g_VTh);
        cudaGetSymbolAddress((void**)&gVTl, g_VTl);
        cudaGetSymbolAddress((void**)&gQh,  g_Qh);
        cudaGetSymbolAddress((void**)&gQl,  g_Ql);
        cudaGetSymbolAddress((void**)&gAh,  g_Ah);
        cudaGetSymbolAddress((void**)&gAl,  g_Al);
        cudaGetSymbolAddress((void**)&gHth, g_Hth);
        cudaGetSymbolAddress((void**)&gHtl, g_Htl);
        cudaGetSymbolAddress((void**)&gWh,  g_Wh);
        cudaGetSymbolAddress((void**)&gWl,  g_Wl);
        cudaFuncSetAttribute(gemm_mma, cudaFuncAttributeMaxDynamicSharedMemorySize, GEMM_SMEM);
        cudaFuncSetAttribute(kv_gemm, cudaFuncAttributeMaxDynamicSharedMemorySize, GEMM_SMEM);
        init = true;
    }

    const int MT = (L_ + TM - 1) / TM;  // 70

    // 0) splits / transpose
    split_q<<<dim3(L_), 256>>>(Q);
    ht_split<<<dim3(S_ / 32, D_ / 64, B_), dim3(32, 8)>>>(H);
    w_split<<<dim3(2 * D_ * D_ / 1024), 256>>>(Wk, Wv);

    // 1a) K[b,s,o] = H^T * Wk
    kv_gemm<<<dim3(D_ / TN, S_ / TM, B_), 256, GEMM_SMEM>>>(
        gHth, gHtl, D_, (size_t)S_ * D_,
        gWh, gWl, D_, 0,
        gKh, gKl, D_, (size_t)S_ * D_,
        bk, 0, D_ / TK);

    // 1b) V^T[b,o,s] = Wv * H^T
    kv_gemm<<<dim3(S_ / TN, D_ / TM, B_), 256, GEMM_SMEM>>>(
        gWh + D_ * D_, gWl + D_ * D_, D_, 0,
        gHth, gHtl, D_, (size_t)S_ * D_,
        gVTh, gVTl, S_, (size_t)D_ * S_,
        bv, 1, D_ / TK);

    // 2) E = Q K^T -> Aout
    gemm_mma<<<dim3(S_ / TN, MT, B_), 256, GEMM_SMEM>>>(
        gQh, gQl, D_, 0,
        gKh, gKl, D_, (size_t)S_ * D_,
        Aout, S_, (size_t)L_ * S_,
        D_ / TK, L_);

    // 3) softmax rows (+ bf16x2 split of A)
    softmax_kernel<<<dim3(B_ * L_), 256>>>(Aout);

    // 4) C = A V -> Cout
    gemm_mma<<<dim3(D_ / TN, MT, B_), 256, GEMM_SMEM>>>(
        gAh, gAl, S_, (size_t)L_ * S_,
        gVTh, gVTl, S_, (size_t)D_ * S_,
        Cout, D_, (size_t)L_ * D_,
        S_ / TK, L_);
}